// round 2
// baseline (speedup 1.0000x reference)
#include <cuda_runtime.h>

// Problem constants (YOLO loss, S=7, P=2, C=20)
#define S7      7
#define NCELL   49
#define BATCHN  16384
#define DCH     30
#define TOTALC  (BATCHN * NCELL)      // 802816 cells
#define CPB     128                   // cells per block (pass 1)
#define NCHUNK  (TOTALC / CPB)        // 6272 chunks (exact)
#define K1_BLOCKS 1036

// Scratch (static device allocations are allowed)
__device__ float g_G[NCELL];          // per-cell coefficient of `has`
__device__ float g_C;                 // global constant term
__device__ float g_has[TOTALC];       // has, transposed: [cell_s][batch]

__global__ void zero_kernel() {
    int t = threadIdx.x;
    if (t < NCELL) g_G[t] = 0.f;
    if (t == NCELL) g_C = 0.f;
}

// img_width/img_height may arrive as int32 or float32 scalars; decide by bit pattern.
// (448 as float = 0x43E00000 = 1139015680, far above the int guard band.)
__device__ __forceinline__ float dimval(const void* p) {
    int iv = *(const int*)p;
    if (iv > 0 && iv < 1000000) return (float)iv;
    return *(const float*)p;
}

__global__ __launch_bounds__(CPB)
void yolo_cell_kernel(const float* __restrict__ outp,
                      const float* __restrict__ tgtp,
                      const void* __restrict__ wp,
                      const void* __restrict__ hp)
{
    __shared__ float s_out[CPB * DCH];     // 15360 B
    __shared__ float s_tgt[CPB * DCH];     // 15360 B
    __shared__ float sh_G[NCELL];
    __shared__ float sh_C;

    const int t = threadIdx.x;
    if (t < NCELL) sh_G[t] = 0.f;
    if (t == 0) sh_C = 0.f;

    const float W = wp ? dimval(wp) : 448.f;
    const float H = hp ? dimval(hp) : 448.f;
    const float fw = W * (1.f / 7.f);
    const float fh = H * (1.f / 7.f);

    for (int chunk = blockIdx.x; chunk < NCHUNK; chunk += gridDim.x) {
        __syncthreads();   // orders smem init / previous iteration's readers

        // ---- stage 128 cells (3840 floats per array) via coalesced float4 ----
        {
            const float4* __restrict__ go = (const float4*)(outp + (size_t)chunk * CPB * DCH);
            const float4* __restrict__ gt = (const float4*)(tgtp + (size_t)chunk * CPB * DCH);
            float4* so4 = (float4*)s_out;
            float4* st4 = (float4*)s_tgt;
            #pragma unroll
            for (int i = 0; i < CPB * DCH / 4 / CPB; i++) {
                so4[i * CPB + t] = go[i * CPB + t];
                st4[i * CPB + t] = gt[i * CPB + t];
            }
            // remainder: 3840/4 = 960 = 7*128 + 64
            if (t < 64) {
                so4[7 * CPB + t] = go[7 * CPB + t];
                st4[7 * CPB + t] = gt[7 * CPB + t];
            }
        }
        __syncthreads();

        // ---- per-thread cell compute ----
        const int c  = chunk * CPB + t;
        const int s  = c % NCELL;
        const int b  = c / NCELL;
        const int ri = s / 7;      // row index
        const int cj = s % 7;      // col index

        // stride 120B => 8-byte aligned, LDS.64 conflict-free
        const float2* so = (const float2*)(s_out + t * DCH);
        const float2* st = (const float2*)(s_tgt + t * DCH);
        float2 o01 = so[0], o23 = so[1], o45 = so[2], o67 = so[3], o89 = so[4];
        float2 t01 = st[0], t23 = st[1], t45 = st[2];

        const float tx = t01.x, ty = t01.y;
        const float tw = t23.x * W, th = t23.y * H;
        const float has = t45.x;

        // target box (reference decode, literally)
        const float tcx = ((float)cj + tx) * fw;
        const float tcy = ((float)ri + ty) * fh;
        const float tx0 = tcx - tw * 0.5f, tx1 = tcx + tw * 0.5f;
        const float ty0 = tcy - th * 0.5f, ty1 = tcy + th * 0.5f;
        const float areaT = (tx1 - tx0) * (ty1 - ty0);

        float iou0, iou1;
        {   // predictor 0: x=o[0] y=o[1] w=o[3]*W h=o[4]*H
            float cx = ((float)cj + o01.x) * fw;
            float cy = ((float)ri + o01.y) * fh;
            float pw = o23.y * W, ph = o45.x * H;
            float x0 = cx - pw * 0.5f, x1 = cx + pw * 0.5f;
            float y0 = cy - ph * 0.5f, y1 = cy + ph * 0.5f;
            float iw = fmaxf(fminf(x1, tx1) - fmaxf(x0, tx0), 0.f);
            float ih = fmaxf(fminf(y1, ty1) - fmaxf(y0, ty0), 0.f);
            float inter = iw * ih;
            float area = (x1 - x0) * (y1 - y0);
            iou0 = inter / (area + areaT - inter + 1e-9f);
        }
        {   // predictor 1: x=o[5] y=o[6] w=o[8]*W h=o[9]*H
            float cx = ((float)cj + o45.y) * fw;
            float cy = ((float)ri + o67.x) * fh;
            float pw = o89.x * W, ph = o89.y * H;
            float x0 = cx - pw * 0.5f, x1 = cx + pw * 0.5f;
            float y0 = cy - ph * 0.5f, y1 = cy + ph * 0.5f;
            float iw = fmaxf(fminf(x1, tx1) - fmaxf(x0, tx0), 0.f);
            float ih = fmaxf(fminf(y1, ty1) - fmaxf(y0, ty0), 0.f);
            float inter = iw * ih;
            float area = (x1 - x0) * (y1 - y0);
            iou1 = inter / (area + areaT - inter + 1e-9f);
        }

        // best = P-1 - argmax([iou1, iou0]); ties -> first => iou1>=iou0 picks 1
        const float conf0 = o45.x;   // out[4]
        const float conf1 = o89.y;   // out[9]
        const float best_conf = (iou1 >= iou0) ? conf1 : conf0;

        // coord/conf losses for predictor L = P-1 = 1
        const float px = o45.y, py = o67.x;
        const float pw = o89.x * W, ph = o89.y * H;
        const float dx = tx - px, dy = ty - py;
        const float dw = sqrtf(tw) - sqrtf(pw);
        const float dh = sqrtf(th) - sqrtf(ph);
        const float ab = dx * dx + dy * dy + dw * dw + dh * dh;
        const float dc = has - o89.y;          // t_conf - p_conf (p_conf = out[9])
        const float cm = dc * dc;

        // class mse with best_conf scaling: channels 10..29 = float2 idx 5..14
        float km = 0.f;
        #pragma unroll
        for (int k = 0; k < 10; k++) {
            float2 oc = so[5 + k];
            float2 tc = st[5 + k];
            float d0 = tc.x - oc.x * best_conf;
            float d1 = tc.y - oc.y * best_conf;
            km = fmaf(d0, d0, km);
            km = fmaf(d1, d1, km);
        }

        // stash has transposed for coalesced pass-2 reads
        g_has[s * BATCHN + b] = has;

        // per-cell coefficient of has: 5*(x+y+w+h) + (1 - 0.5)*conf_mse
        atomicAdd(&sh_G[s], fmaf(5.f, ab, 0.5f * cm));

        // constant term: 0.5*conf_mse + class_mse  (warp-reduce, 1 atomic/warp)
        float cterm = fmaf(0.5f, cm, km);
        #pragma unroll
        for (int o = 16; o > 0; o >>= 1)
            cterm += __shfl_down_sync(0xffffffffu, cterm, o);
        if ((t & 31) == 0) atomicAdd(&sh_C, cterm);
    }

    __syncthreads();
    if (t < NCELL) atomicAdd(&g_G[t], sh_G[t]);
    if (t == 0) atomicAdd(&g_C, sh_C);
}

__global__ __launch_bounds__(256)
void finalize_kernel(float* __restrict__ loss)
{
    __shared__ float sG[NCELL];
    __shared__ float sC;
    const int t = threadIdx.x;
    if (t < NCELL) sG[t] = g_G[t];
    if (t == NCELL) sC = g_C;
    __syncthreads();

    const int b = blockIdx.x * blockDim.x + t;
    float acc = sC;
    #pragma unroll
    for (int s = 0; s < NCELL; s++)
        acc = fmaf(sG[s], g_has[s * BATCHN + b], acc);
    loss[b] = acc;
}

extern "C" void kernel_launch(void* const* d_in, const int* in_sizes, int n_in,
                              void* d_out, int out_size)
{
    const float* outp = (const float*)d_in[0];
    const float* tgtp = (const float*)d_in[1];
    const void* wp = (n_in >= 3) ? d_in[2] : nullptr;
    const void* hp = (n_in >= 4) ? d_in[3] : nullptr;
    float* loss = (float*)d_out;

    zero_kernel<<<1, 64>>>();
    int grid = NCHUNK < K1_BLOCKS ? NCHUNK : K1_BLOCKS;
    yolo_cell_kernel<<<grid, CPB>>>(outp, tgtp, wp, hp);
    finalize_kernel<<<BATCHN / 256, 256>>>(loss);
}

// round 5
// speedup vs baseline: 1.1304x; 1.1304x over previous
#include <cuda_runtime.h>
#include <cuda_pipeline_primitives.h>
#include <cstdint>

// Problem constants (YOLO loss, S=7, P=2, C=20)
#define NCELL   49
#define BATCHN  16384
#define DCH     30
#define TOTALC  (BATCHN * NCELL)        // 802816 cells
#define CPB     98                      // cells per block-chunk (802816/98 = 8192 exact)
#define NCHUNK  (TOTALC / CPB)          // 8192 chunks
#define TPB     128                     // threads per block (98 compute-active)
#define GRID1   592                     // 4 blocks/SM * 148 SMs
#define CHUNK_FLOATS (CPB * DCH)        // 2940 floats per array per chunk
#define CHUNK_F4     (CHUNK_FLOATS / 4) // 735 float4
#define BUF_FLOATS   (2 * CHUNK_FLOATS) // out + tgt per buffer = 5880 floats

// Scratch
__device__ float g_P[50 * GRID1];       // per-block partials: rows 0..48 = G[s], row 49 = C
__device__ float g_has[TOTALC];         // has, LINEAR order (coalesced store)

// img_width/img_height may arrive as int32 or float32 scalars; decide by bit pattern.
__device__ __forceinline__ float dimval(const void* p) {
    int iv = *(const int*)p;
    if (iv > 0 && iv < 1000000) return (float)iv;
    return *(const float*)p;
}

// Stage one chunk (out + tgt, 735 float4 each) with all 128 threads.
__device__ __forceinline__ void stage_chunk(float* sbuf, const float* __restrict__ outp,
                                            const float* __restrict__ tgtp,
                                            int chunk, int t)
{
    const float4* go = (const float4*)(outp + (size_t)chunk * CHUNK_FLOATS);
    const float4* gt = (const float4*)(tgtp + (size_t)chunk * CHUNK_FLOATS);
    float4* so = (float4*)sbuf;
    float4* st = (float4*)(sbuf + CHUNK_FLOATS);
    #pragma unroll
    for (int i = 0; i < 5; i++) {       // 5*128 = 640
        __pipeline_memcpy_async(&so[i * TPB + t], &go[i * TPB + t], 16);
        __pipeline_memcpy_async(&st[i * TPB + t], &gt[i * TPB + t], 16);
    }
    if (t < CHUNK_F4 - 5 * TPB) {       // remainder 95
        __pipeline_memcpy_async(&so[5 * TPB + t], &go[5 * TPB + t], 16);
        __pipeline_memcpy_async(&st[5 * TPB + t], &gt[5 * TPB + t], 16);
    }
}

__global__ __launch_bounds__(TPB)
void yolo_cell_kernel(const float* __restrict__ outp,
                      const float* __restrict__ tgtp,
                      const void* __restrict__ wp,
                      const void* __restrict__ hp)
{
    __shared__ __align__(16) float smem[2 * BUF_FLOATS];   // 47040 B, double buffer
    __shared__ float sh_G[NCELL];
    __shared__ float sh_C;

    const int t = threadIdx.x;
    if (t < NCELL) sh_G[t] = 0.f;
    if (t == NCELL) sh_C = 0.f;

    const float W = wp ? dimval(wp) : 448.f;
    const float H = hp ? dimval(hp) : 448.f;
    const float fw = W * (1.f / 7.f);
    const float fh = H * (1.f / 7.f);

    // prologue: stage first chunk into buffer 0
    int chunk = blockIdx.x;
    stage_chunk(smem, outp, tgtp, chunk, t);
    __pipeline_commit();

    int buf = 0;
    for (; chunk < NCHUNK; chunk += GRID1) {
        const int next = chunk + GRID1;
        // stage next chunk into the other buffer (overlaps with compute below)
        if (next < NCHUNK) stage_chunk(smem + (buf ^ 1) * BUF_FLOATS, outp, tgtp, next, t);
        __pipeline_commit();
        if (next < NCHUNK) __pipeline_wait_prior(1);
        else               __pipeline_wait_prior(0);
        __syncthreads();

        // ---- per-thread cell compute from buffer `buf` (threads 0..97 active) ----
        float cterm = 0.f;
        if (t < CPB) {
            const float* s_out = smem + buf * BUF_FLOATS;
            const float* s_tgt = s_out + CHUNK_FLOATS;

            const int c  = chunk * CPB + t;
            const int s  = c % NCELL;
            const int ri = s / 7;
            const int cj = s % 7;

            const float2* so = (const float2*)(s_out + t * DCH);
            const float2* st = (const float2*)(s_tgt + t * DCH);
            float2 o01 = so[0], o23 = so[1], o45 = so[2], o67 = so[3], o89 = so[4];
            float2 t01 = st[0], t23 = st[1], t45 = st[2];

            const float tx = t01.x, ty = t01.y;
            const float tw = t23.x * W, th = t23.y * H;
            const float has = t45.x;

            // target box (reference decode, literally)
            const float tcx = ((float)cj + tx) * fw;
            const float tcy = ((float)ri + ty) * fh;
            const float tx0 = tcx - tw * 0.5f, tx1 = tcx + tw * 0.5f;
            const float ty0 = tcy - th * 0.5f, ty1 = tcy + th * 0.5f;
            const float areaT = (tx1 - tx0) * (ty1 - ty0);

            float iou0, iou1;
            {   // predictor 0: x=o[0] y=o[1] w=o[3]*W h=o[4]*H
                float cx = ((float)cj + o01.x) * fw;
                float cy = ((float)ri + o01.y) * fh;
                float pw = o23.y * W, ph = o45.x * H;
                float x0 = cx - pw * 0.5f, x1 = cx + pw * 0.5f;
                float y0 = cy - ph * 0.5f, y1 = cy + ph * 0.5f;
                float iw = fmaxf(fminf(x1, tx1) - fmaxf(x0, tx0), 0.f);
                float ih = fmaxf(fminf(y1, ty1) - fmaxf(y0, ty0), 0.f);
                float inter = iw * ih;
                float area = (x1 - x0) * (y1 - y0);
                iou0 = inter / (area + areaT - inter + 1e-9f);
            }
            {   // predictor 1: x=o[5] y=o[6] w=o[8]*W h=o[9]*H
                float cx = ((float)cj + o45.y) * fw;
                float cy = ((float)ri + o67.x) * fh;
                float pw = o89.x * W, ph = o89.y * H;
                float x0 = cx - pw * 0.5f, x1 = cx + pw * 0.5f;
                float y0 = cy - ph * 0.5f, y1 = cy + ph * 0.5f;
                float iw = fmaxf(fminf(x1, tx1) - fmaxf(x0, tx0), 0.f);
                float ih = fmaxf(fminf(y1, ty1) - fmaxf(y0, ty0), 0.f);
                float inter = iw * ih;
                float area = (x1 - x0) * (y1 - y0);
                iou1 = inter / (area + areaT - inter + 1e-9f);
            }

            // best = P-1 - argmax([iou1, iou0]); ties -> first => iou1>=iou0 picks 1
            const float best_conf = (iou1 >= iou0) ? o89.y : o45.x;

            // coord/conf losses for predictor L = 1
            const float px = o45.y, py = o67.x;
            const float pw = o89.x * W, ph = o89.y * H;
            const float dx = tx - px, dy = ty - py;
            const float dw = sqrtf(tw) - sqrtf(pw);
            const float dh = sqrtf(th) - sqrtf(ph);
            const float ab = dx * dx + dy * dy + dw * dw + dh * dh;
            const float dc = has - o89.y;         // t_conf - p_conf (p_conf = out[9])
            const float cm = dc * dc;

            // class mse with best_conf scaling: channels 10..29 = float2 idx 5..14
            float km = 0.f;
            #pragma unroll
            for (int k = 0; k < 10; k++) {
                float2 oc = so[5 + k];
                float2 tc = st[5 + k];
                float d0 = tc.x - oc.x * best_conf;
                float d1 = tc.y - oc.y * best_conf;
                km = fmaf(d0, d0, km);
                km = fmaf(d1, d1, km);
            }

            // linear (coalesced) has stash for finalize
            g_has[c] = has;

            // per-cell coefficient of has: 5*(x+y+w+h) + (1 - 0.5)*conf_mse
            atomicAdd(&sh_G[s], fmaf(5.f, ab, 0.5f * cm));

            // constant term: 0.5*conf_mse + class_mse
            cterm = fmaf(0.5f, cm, km);
        }

        // warp-reduce cterm (inactive lanes contribute 0), 1 atomic/warp
        #pragma unroll
        for (int o = 16; o > 0; o >>= 1)
            cterm += __shfl_down_sync(0xffffffffu, cterm, o);
        if ((t & 31) == 0) atomicAdd(&sh_C, cterm);

        buf ^= 1;
        __syncthreads();   // all readers done before this buffer is restaged
    }

    __syncthreads();
    // non-atomic per-block partials: rows 0..48 = G, row 49 = C
    if (t < NCELL) g_P[t * GRID1 + blockIdx.x] = sh_G[t];
    if (t == NCELL) g_P[NCELL * GRID1 + blockIdx.x] = sh_C;
}

__global__ __launch_bounds__(256)
void finalize_kernel(float* __restrict__ loss)
{
    __shared__ float sR[50];
    const int t = threadIdx.x;
    const int w = t >> 5, lane = t & 31;

    // redundant per-block reduction of partials (L2-resident, 50x592)
    for (int row = w; row < 50; row += 8) {
        const float* p = g_P + row * GRID1;
        float acc = 0.f;
        #pragma unroll
        for (int k = 0; k < 19; k++) {
            int idx = lane + 32 * k;
            if (idx < GRID1) acc += p[idx];
        }
        #pragma unroll
        for (int o = 16; o > 0; o >>= 1)
            acc += __shfl_down_sync(0xffffffffu, acc, o);
        if (lane == 0) sR[row] = acc;
    }
    __syncthreads();

    const int b = blockIdx.x * 256 + t;
    const float* hb = g_has + (size_t)b * NCELL;
    float acc = sR[49];                 // constant term
    #pragma unroll
    for (int s = 0; s < NCELL; s++)
        acc = fmaf(sR[s], hb[s], acc);
    loss[b] = acc;
}

extern "C" void kernel_launch(void* const* d_in, const int* in_sizes, int n_in,
                              void* d_out, int out_size)
{
    const float* outp = (const float*)d_in[0];
    const float* tgtp = (const float*)d_in[1];
    const void* wp = (n_in >= 3) ? d_in[2] : nullptr;
    const void* hp = (n_in >= 4) ? d_in[3] : nullptr;
    float* loss = (float*)d_out;

    yolo_cell_kernel<<<GRID1, TPB>>>(outp, tgtp, wp, hp);
    finalize_kernel<<<BATCHN / 256, 256>>>(loss);
}